// round 17
// baseline (speedup 1.0000x reference)
#include <cuda_runtime.h>
#include <cuda_fp16.h>
#include <math.h>
#include <stdint.h>

#define NROWS 4096
#define NC    256
#define TM    64            // rows per MLP block
#define KT    32            // k per pipeline stage

// smem layout (bytes)
#define STG    25600        // stage: A 64x80 | W 256x80
#define A_OFF  0
#define W_OFF  5120
#define H_OFF  51200        // H: 64 rows x 528B
#define RS_OFF 84992        // rowsum[64] float
#define SMEM_TOTAL 85248

// ---------------- scratch ----------------
__device__ __align__(16) __half g_Xh[4096 * 1792];
__device__ __align__(16) __half g_W1h[256 * 1792];
__device__ __align__(16) __half g_W2h[3 * 256 * 256];
__device__ int g_ctr[4];                    // per-level producer counters

// ---------------- asm helpers ----------------
__device__ __forceinline__ uint32_t smem_u32(const void* p) {
    uint32_t a;
    asm("{ .reg .u64 t; cvta.to.shared.u64 t, %1; cvt.u32.u64 %0, t; }" : "=r"(a) : "l"(p));
    return a;
}
#define LDSM_X4(r0, r1, r2, r3, addr) \
    asm volatile("ldmatrix.sync.aligned.m8n8.x4.shared.b16 {%0,%1,%2,%3}, [%4];" \
        : "=r"(r0), "=r"(r1), "=r"(r2), "=r"(r3) : "r"(addr))
#define MMA16816(d, a, b0v, b1v) \
    asm volatile("mma.sync.aligned.m16n8k16.row.col.f32.f16.f16.f32 " \
        "{%0,%1,%2,%3}, {%4,%5,%6,%7}, {%8,%9}, {%0,%1,%2,%3};" \
        : "+f"((d)[0]), "+f"((d)[1]), "+f"((d)[2]), "+f"((d)[3]) \
        : "r"((a)[0]), "r"((a)[1]), "r"((a)[2]), "r"((a)[3]), "r"(b0v), "r"(b1v))
#define CP16(dst, src) \
    asm volatile("cp.async.cg.shared.global [%0], [%1], 16;" :: "r"(dst), "l"(src))
#define CP_COMMIT() asm volatile("cp.async.commit_group;" ::: "memory")
#define CP_WAIT0()  asm volatile("cp.async.wait_group 0;" ::: "memory")
#define CP_WAIT1()  asm volatile("cp.async.wait_group 1;" ::: "memory")

// verified MMA mapping (R6..R15)
__device__ __forceinline__ void mma_step16(
    uint32_t aBase, int strA, uint32_t aCol,
    uint32_t wBase, int strW, uint32_t wCol, int lr,
    float (&acc)[8][4])
{
    uint32_t a[4];
    LDSM_X4(a[0], a[1], a[2], a[3], aBase + lr * strA + aCol);
#pragma unroll
    for (int go = 0; go < 2; go++) {
        uint32_t b[2][4];
#pragma unroll
        for (int g = 0; g < 2; g++)
            LDSM_X4(b[g][0], b[g][1], b[g][2], b[g][3],
                    wBase + ((go * 2 + g) * 16 + lr) * strW + wCol);
#pragma unroll
        for (int nl = 0; nl < 4; nl++) {
            const int nb = go * 4 + nl;
            const int g = nl >> 1, h = nl & 1;
            MMA16816(acc[nb], a, b[g][h], b[g][h + 2]);
        }
    }
}

// ---------------- fused pipeline kernel ----------------
struct AllParams {
    const float* feat[3];
    const void*  pid[3];
    const float* W1[3];
    const float* W2[3];
    const float* bias1[3];
    const float* bias2[3];
    int    C[3];
    int    HW[3];
    size_t xoff[3];
    size_t w1off[3];
    float* out;
};

__global__ void __launch_bounds__(512, 2) fused_all(AllParams p) {
    extern __shared__ __align__(16) char dsm[];
    const uint32_t sb = smem_u32(dsm);
    const int tid = threadIdx.x;
    const int bx = blockIdx.x;

    // role decode: [0,80) wcvt | then per level (2,1,0): 256 gather + 64 mlp
    int lvl, role, idx;
    if (bx < 80) {
        role = 0;
        lvl = (bx < 40) ? 2 : (bx < 64) ? 1 : 0;
        idx = (bx < 40) ? bx : (bx < 64) ? bx - 40 : bx - 64;
    } else {
        const int g = bx - 80;
        const int seg = g / 320, off = g % 320;
        lvl = 2 - seg;
        if (off < 256) { role = 1; idx = off; }
        else           { role = 2; idx = off - 256; }
    }
    const int C  = p.C[lvl];
    const int HW = p.HW[lvl];

    if (role == 0) {
        // ---------------- wcvt strip (dynamic smem) ----------------
        float (*s)[257] = (float(*)[257])dsm;
        int strip = idx;
        const int nW1 = C / 32;
        const float* W;
        __half* out;
        int K, kb;
        if (strip < nW1) {
            W = p.W1[lvl]; K = C;
            out = g_W1h + p.w1off[lvl];
            kb = strip * 32;
        } else {
            strip -= nW1;
            W = p.W2[lvl]; K = NC;
            out = g_W2h + (size_t)lvl * 65536;
            kb = strip * 32;
        }
#pragma unroll
        for (int j = 0; j < 4; j++) {
            const int job = tid + 512 * j;          // 2048 float4 jobs
            const int r = job >> 6, c4 = job & 63;
            const float4 v = *(const float4*)(W + (size_t)(kb + r) * NC + c4 * 4);
            s[r][c4 * 4 + 0] = v.x;
            s[r][c4 * 4 + 1] = v.y;
            s[r][c4 * 4 + 2] = v.z;
            s[r][c4 * 4 + 3] = v.w;
        }
        __syncthreads();
        const int tx = tid & 31, ty = tid >> 5;     // ty 0..15
#pragma unroll
        for (int pass = 0; pass < 16; pass++) {
            const int n = pass * 16 + ty;
            out[(size_t)n * K + kb + tx] = __float2half(s[tx][n]);
        }
        __syncthreads();
        __threadfence();
        if (tid == 0) atomicAdd(&g_ctr[lvl], 1);
        return;
    }

    if (role == 1) {
        // ---------------- gather: 16 rows per block, warp per row ----------------
        const int w = tid >> 5, l = tid & 31;
        const int row = idx * 16 + w;
        const int* pw = (const int*)p.pid[lvl];
        bool i64 = true;
#pragma unroll
        for (int i = 1; i < 64; i += 2) i64 = i64 && (pw[i] == 0);
        long long pid = i64 ? ((const long long*)p.pid[lvl])[row & 255]
                            : (long long)pw[row & 255];
        if (pid < 0)  pid = 0;
        if (pid >= HW) pid = HW - 1;
        const float* src = p.feat[lvl] + (size_t)(row >> 8) * C * HW + (size_t)pid;
        __half* dst = g_Xh + p.xoff[lvl] + (size_t)row * C;

        const int nj = C >> 6;                      // 4 / 8 / 16
        for (int j0 = 0; j0 < nj; j0 += 8) {
            float xa[8], xb[8];
#pragma unroll
            for (int j = 0; j < 8; j++) {
                if (j0 + j < nj) {
                    const int c = 2 * l + 64 * (j0 + j);
                    xa[j] = __ldcg(src + (size_t)c * HW);
                    xb[j] = __ldcg(src + (size_t)(c + 1) * HW);
                }
            }
#pragma unroll
            for (int j = 0; j < 8; j++) {
                if (j0 + j < nj) {
                    const int c = 2 * l + 64 * (j0 + j);
                    __half2 h = __floats2half2_rn(xa[j], xb[j]);
                    *(__half2*)(dst + c) = h;
                }
            }
        }
        __syncthreads();
        __threadfence();
        if (tid == 0) atomicAdd(&g_ctr[lvl], 1);
        return;
    }

    // ---------------- MLP consumer ----------------
    {
        static const int targets[3] = { 272, 280, 296 };  // 256 gather + wcvt strips
        if (tid == 0) {
            const int tgt = targets[lvl];
            while (*(volatile int*)&g_ctr[lvl] < tgt) __nanosleep(200);
        }
        __syncthreads();
        __threadfence();
    }

    const int K = C;
    const int rowBase = idx * TM;
    const int wid = tid >> 5;
    const int lid = tid & 31;
    const int lr  = lid & 15;
    const int lcx = (lid >> 4) * 16;
    const int warpM = (wid >> 2) * 16;
    const int warpN = (wid & 3) * 64;

    const __half* Xr = g_Xh + p.xoff[lvl] + (size_t)rowBase * K;
    const __half* W1 = g_W1h + p.w1off[lvl];
    const __half* W2 = g_W2h + (size_t)lvl * 65536;

    if (tid < TM) *(float*)(dsm + RS_OFF + tid * 4) = 0.0f;
    __syncthreads();

    auto loadA = [&](int t, int buf) {
        if (tid < 256) {
            const int r = tid >> 2, ch = tid & 3;
            CP16(sb + buf * STG + A_OFF + r * 80 + ch * 16,
                 Xr + (size_t)r * K + t * KT + ch * 8);
        }
    };
    auto loadW = [&](const __half* Wg, int Kw, int t, int buf) {
#pragma unroll
        for (int j = 0; j < 2; j++) {
            const int job = tid + 512 * j;
            const int n = job >> 2, ch = job & 3;
            CP16(sb + buf * STG + W_OFF + n * 80 + ch * 16,
                 Wg + (size_t)n * Kw + t * KT + ch * 8);
        }
    };

    float acc[8][4];
#pragma unroll
    for (int nb = 0; nb < 8; nb++)
#pragma unroll
        for (int j = 0; j < 4; j++) acc[nb][j] = 0.0f;

    // layer 1
    const int nk1 = K / KT;
    loadA(0, 0); loadW(W1, K, 0, 0); CP_COMMIT();
    for (int t = 0; t < nk1; t++) {
        const int buf = t & 1;
        if (t + 1 < nk1) {
            loadA(t + 1, buf ^ 1); loadW(W1, K, t + 1, buf ^ 1); CP_COMMIT();
            CP_WAIT1();
        } else {
            CP_WAIT0();
        }
        __syncthreads();
        const uint32_t base = sb + buf * STG;
#pragma unroll
        for (int kk = 0; kk < 2; kk++)
            mma_step16(base + A_OFF + warpM * 80, 80, kk * 32 + lcx,
                       base + W_OFF + warpN * 80, 80, kk * 32 + lcx, lr, acc);
        __syncthreads();
    }

    // epilogue-1 + W2 prefetch
    loadW(W2, 256, 0, 0); CP_COMMIT();
    {
        const float* b1 = p.bias1[lvl];
#pragma unroll
        for (int nb = 0; nb < 8; nb++) {
            const int c = warpN + (lid & 3) * 2 + nb * 8;
            const float bx_ = b1[c], by_ = b1[c + 1];
#pragma unroll
            for (int hr = 0; hr < 2; hr++) {
                const int r = warpM + hr * 8 + (lid >> 2);
                float v0 = fmaxf(acc[nb][hr * 2]     + bx_, 0.0f);
                float v1 = fmaxf(acc[nb][hr * 2 + 1] + by_, 0.0f);
                __half2 h = __floats2half2_rn(v0, v1);
                *(uint32_t*)(dsm + H_OFF + r * 528 + c * 2) = *(uint32_t*)&h;
            }
        }
    }
#pragma unroll
    for (int nb = 0; nb < 8; nb++)
#pragma unroll
        for (int j = 0; j < 4; j++) acc[nb][j] = 0.0f;

    // layer 2
    for (int t = 0; t < 8; t++) {
        const int buf = t & 1;
        if (t + 1 < 8) { loadW(W2, 256, t + 1, buf ^ 1); CP_COMMIT(); CP_WAIT1(); }
        else           { CP_WAIT0(); }
        __syncthreads();
        const uint32_t base = sb + buf * STG;
#pragma unroll
        for (int kk = 0; kk < 2; kk++)
            mma_step16(sb + H_OFF + warpM * 528, 528, (t * 32 + kk * 16) * 2 + lcx,
                       base + W_OFF + warpN * 80, 80, kk * 32 + lcx, lr, acc);
        __syncthreads();
    }

    // epilogue-2
    {
        const float* b2 = p.bias2[lvl];
        float* rowsum = (float*)(dsm + RS_OFF);
#pragma unroll
        for (int hr = 0; hr < 2; hr++) {
            float part = 0.0f;
#pragma unroll
            for (int nb = 0; nb < 8; nb++) {
                const int c = warpN + (lid & 3) * 2 + nb * 8;
                float v0 = acc[nb][hr * 2]     + b2[c];
                float v1 = acc[nb][hr * 2 + 1] + b2[c + 1];
                acc[nb][hr * 2]     = v0;
                acc[nb][hr * 2 + 1] = v1;
                part += v0 * v0 + v1 * v1;
            }
            atomicAdd(&rowsum[warpM + hr * 8 + (lid >> 2)], part);
        }
        __syncthreads();
        float* O = p.out + (size_t)lvl * NROWS * NC;
#pragma unroll
        for (int hr = 0; hr < 2; hr++) {
            const int r = warpM + hr * 8 + (lid >> 2);
            const float sc = 1.0f / (sqrtf(rowsum[r]) + 1e-7f);
#pragma unroll
            for (int nb = 0; nb < 8; nb++) {
                const int c = warpN + (lid & 3) * 2 + nb * 8;
                float2 o;
                o.x = acc[nb][hr * 2]     * sc;
                o.y = acc[nb][hr * 2 + 1] * sc;
                *(float2*)(O + (size_t)(rowBase + r) * NC + c) = o;
            }
        }
    }
}

// ---------------- host ----------------
#define F0 67108864LL
#define F1 33554432LL
#define F2 16777216LL
#define W10 65536LL
#define W11 131072LL
#define W12 262144LL
#define SB  256LL

static inline bool ok_sz(long long actual, long long elems) {
    return actual == elems || actual == elems * 4 || actual == elems * 8;
}

extern "C" void kernel_launch(void* const* d_in, const int* in_sizes, int n_in,
                              void* d_out, int out_size) {
    (void)out_size;
    static const int CS[3]  = {256, 512, 1024};
    static const int HWS[3] = {128 * 128, 64 * 64, 32 * 32};
    static const size_t XOFF[3]  = {0, (size_t)4096 * 256, (size_t)4096 * 768};
    static const size_t W1OFF[3] = {0, (size_t)256 * 256, (size_t)256 * 768};

    static void* s_ctr = nullptr;
    if (!s_ctr) {
        cudaFuncSetAttribute(fused_all,
                             cudaFuncAttributeMaxDynamicSharedMemorySize, SMEM_TOTAL);
        cudaGetSymbolAddress(&s_ctr, g_ctr);
    }

    static const int ORD_DICT[18]  = { 0,1,2,3,4,5,  6,7,8,9,10,11,  12,13,14,15,16,17 };
    static const int ORD_SIG[18]   = { 0,3,6,7,8,9,  1,4,10,11,12,13,  2,5,14,15,16,17 };
    static const int ORD_ALPHA[18] = { 6,9,12,0,15,3,  7,10,13,1,16,4,  8,11,14,2,17,5 };

    const long long featsz[3] = { F0, F1, F2 };
    const long long w1sz[3]   = { W10, W11, W12 };

    const int* cand[3] = { ORD_DICT, ORD_SIG, ORD_ALPHA };
    const int* ord = nullptr;
    for (int c = 0; c < 3 && !ord; c++) {
        bool ok = (n_in >= 18);
        for (int l = 0; l < 3 && ok; l++) {
            const int* m = cand[c] + 6 * l;
            ok = ok && ok_sz(in_sizes[m[0]], featsz[l])
                    && ok_sz(in_sizes[m[1]], SB)
                    && ok_sz(in_sizes[m[2]], w1sz[l])
                    && ok_sz(in_sizes[m[3]], SB)
                    && ok_sz(in_sizes[m[4]], W10)
                    && ok_sz(in_sizes[m[5]], SB);
        }
        if (ok) ord = cand[c];
    }

    int fi[3] = {-1,-1,-1}, pi[3] = {-1,-1,-1}, w1i[3] = {-1,-1,-1};
    int b1i[3] = {-1,-1,-1}, w2i[3] = {-1,-1,-1}, b2i[3] = {-1,-1,-1};
    if (ord) {
        for (int l = 0; l < 3; l++) {
            const int* m = ord + 6 * l;
            fi[l] = m[0]; pi[l] = m[1]; w1i[l] = m[2];
            b1i[l] = m[3]; w2i[l] = m[4]; b2i[l] = m[5];
        }
    } else {
        int any256 = -1, w2seen = 0, w10seen = 0;
        for (int i = 0; i < n_in; i++) {
            long long s = in_sizes[i];
            if      (ok_sz(s, F0))  fi[0] = i;
            else if (ok_sz(s, F1))  fi[1] = i;
            else if (ok_sz(s, F2))  fi[2] = i;
            else if (ok_sz(s, W11)) w1i[1] = i;
            else if (ok_sz(s, W12)) w1i[2] = i;
            else if (ok_sz(s, W10)) {
                if (!w10seen) { w1i[0] = i; w10seen = 1; }
                else if (w2seen < 3) w2i[w2seen++] = i;
            }
            else if (ok_sz(s, SB) && any256 < 0) any256 = i;
        }
        for (int l = 0; l < 3; l++) {
            if (fi[l] >= 0) {
                int nxt = fi[l] + 1;
                pi[l] = (nxt < n_in && ok_sz(in_sizes[nxt], SB)) ? nxt : any256;
            }
            b1i[l] = any256; b2i[l] = any256;
        }
    }
    for (int l = 0; l < 3; l++) {
        if (fi[l] < 0 || pi[l] < 0 || w1i[l] < 0 || b1i[l] < 0 ||
            w2i[l] < 0 || b2i[l] < 0) return;
    }

    AllParams ap;
    for (int i = 0; i < 3; i++) {
        ap.feat[i]  = (const float*)d_in[fi[i]];
        ap.pid[i]   = d_in[pi[i]];
        ap.W1[i]    = (const float*)d_in[w1i[i]];
        ap.W2[i]    = (const float*)d_in[w2i[i]];
        ap.bias1[i] = (const float*)d_in[b1i[i]];
        ap.bias2[i] = (const float*)d_in[b2i[i]];
        ap.C[i]     = CS[i];
        ap.HW[i]    = HWS[i];
        ap.xoff[i]  = XOFF[i];
        ap.w1off[i] = W1OFF[i];
    }
    ap.out = (float*)d_out;

    cudaMemsetAsync(s_ctr, 0, sizeof(int) * 4);
    fused_all<<<1040, 512, SMEM_TOTAL>>>(ap);
}